// round 3
// baseline (speedup 1.0000x reference)
#include <cuda_runtime.h>

#define N_NODES 100000
#define E_EDGES 1600000
#define FIN 512
#define HC1 64
#define H1 8
#define C2 16
#define NEG_SLOPE 0.2f

// ---------------- scratch (static __device__, allocation-free) ----------------
__device__ float g_h1  [(size_t)N_NODES * HC1];   // x @ W1
__device__ float g_al1s[(size_t)N_NODES * H1];
__device__ float g_al1d[(size_t)N_NODES * H1];
__device__ float g_s1  [(size_t)N_NODES * H1];    // softmax denominators (init = self-loop term)
__device__ float g_acc1[(size_t)N_NODES * HC1];   // unnormalized weighted sum
__device__ float g_h2  [(size_t)N_NODES * C2];
__device__ float g_al2s[(size_t)N_NODES];
__device__ float g_al2d[(size_t)N_NODES];
__device__ float g_s2  [(size_t)N_NODES];
__device__ float g_acc2[(size_t)N_NODES * C2];
__device__ int   g_is64;

// vectorized global reduction (sm_90+): 1 instruction adds 4 floats
__device__ __forceinline__ void red_add_v4(float* ptr, float a, float b, float c, float d) {
    asm volatile(
        "{\n\t"
        ".reg .u64 p;\n\t"
        "cvta.to.global.u64 p, %0;\n\t"
        "red.global.add.v4.f32 [p], {%1, %2, %3, %4};\n\t"
        "}"
        :: "l"(ptr), "f"(a), "f"(b), "f"(c), "f"(d) : "memory");
}

__device__ __forceinline__ float leaky(float e) { return e > 0.f ? e : NEG_SLOPE * e; }

// ---------------- edge dtype detection (int64 vs int32) ----------------
__global__ void detect_kernel(const int* __restrict__ ei_words) {
    __shared__ int nz;
    if (threadIdx.x == 0) nz = 0;
    __syncthreads();
    // if int64 little-endian with values < 2^31, every odd word is 0
    for (int i = threadIdx.x; i < 4096; i += blockDim.x)
        if (ei_words[2 * i + 1] != 0) nz = 1;
    __syncthreads();
    if (threadIdx.x == 0) g_is64 = (nz == 0);
}

__device__ __forceinline__ void load_edge(const void* ei, int gid, int& src, int& dst) {
    if (g_is64) {
        const long long* p = (const long long*)ei;
        src = (int)p[gid];
        dst = (int)p[E_EDGES + gid];
    } else {
        const int* p = (const int*)ei;
        src = p[gid];
        dst = p[E_EDGES + gid];
    }
}

// ---------------- GEMM1: g_h1 = x @ W1  (100000x512 * 512x64) ----------------
// Tiles: BM=128, BN=64, BK=16; 256 threads; per-thread 8x4 register tile.
__global__ __launch_bounds__(256) void gemm1_kernel(const float* __restrict__ x,
                                                    const float* __restrict__ W1) {
    __shared__ float As[16][128];
    __shared__ float Bs[16][64];
    const int tid = threadIdx.x;
    const int block_row = blockIdx.x * 128;
    const int tx = tid & 15;   // column group (4 cols)
    const int ty = tid >> 4;   // row group (8 rows)

    float acc[8][4];
#pragma unroll
    for (int m = 0; m < 8; m++)
#pragma unroll
        for (int n = 0; n < 4; n++) acc[m][n] = 0.f;

    for (int k0 = 0; k0 < FIN; k0 += 16) {
        // A tile: 128 rows x 16 k = 512 float4 -> 2 per thread, stored transposed
#pragma unroll
        for (int p = 0; p < 2; p++) {
            int idx = tid + p * 256;
            int r = idx >> 2, c4 = idx & 3;
            int gr = block_row + r;
            float4 v = make_float4(0.f, 0.f, 0.f, 0.f);
            if (gr < N_NODES)
                v = *(const float4*)(x + (size_t)gr * FIN + k0 + c4 * 4);
            As[c4 * 4 + 0][r] = v.x;
            As[c4 * 4 + 1][r] = v.y;
            As[c4 * 4 + 2][r] = v.z;
            As[c4 * 4 + 3][r] = v.w;
        }
        // B tile: 16 x 64 = 256 float4, one per thread
        {
            int kk = tid >> 4, n4 = tid & 15;
            float4 v = *(const float4*)(W1 + (size_t)(k0 + kk) * 64 + n4 * 4);
            *(float4*)&Bs[kk][n4 * 4] = v;
        }
        __syncthreads();
#pragma unroll
        for (int kk = 0; kk < 16; kk++) {
            float a[8], b[4];
#pragma unroll
            for (int m = 0; m < 8; m++) a[m] = As[kk][ty * 8 + m];
#pragma unroll
            for (int n = 0; n < 4; n++) b[n] = Bs[kk][tx * 4 + n];
#pragma unroll
            for (int m = 0; m < 8; m++)
#pragma unroll
                for (int n = 0; n < 4; n++) acc[m][n] += a[m] * b[n];
        }
        __syncthreads();
    }
#pragma unroll
    for (int m = 0; m < 8; m++) {
        int r = block_row + ty * 8 + m;
        if (r < N_NODES) {
            float4 v = make_float4(acc[m][0], acc[m][1], acc[m][2], acc[m][3]);
            *(float4*)(g_h1 + (size_t)r * 64 + tx * 4) = v;
        }
    }
}

// ---------------- node1: attention logits + self-loop init ----------------
// 8 lanes per node, lane l = head l.
__global__ __launch_bounds__(256) void node1_kernel(const float* __restrict__ a1s,
                                                    const float* __restrict__ a1d) {
    int t = blockIdx.x * blockDim.x + threadIdx.x;
    int i = t >> 3, l = t & 7;
    if (i >= N_NODES) return;
    float4 h0 = *(const float4*)(g_h1 + (size_t)i * 64 + l * 8);
    float4 h1v = *(const float4*)(g_h1 + (size_t)i * 64 + l * 8 + 4);
    const float* as = a1s + l * 8;
    const float* ad = a1d + l * 8;
    float vs = h0.x * as[0] + h0.y * as[1] + h0.z * as[2] + h0.w * as[3] +
               h1v.x * as[4] + h1v.y * as[5] + h1v.z * as[6] + h1v.w * as[7];
    float vd = h0.x * ad[0] + h0.y * ad[1] + h0.z * ad[2] + h0.w * ad[3] +
               h1v.x * ad[4] + h1v.y * ad[5] + h1v.z * ad[6] + h1v.w * ad[7];
    float w = expf(leaky(vs + vd));     // self-loop weight
    g_al1s[i * 8 + l] = vs;
    g_al1d[i * 8 + l] = vd;
    g_s1[i * 8 + l] = w;
    float4 o0 = make_float4(h0.x * w, h0.y * w, h0.z * w, h0.w * w);
    float4 o1 = make_float4(h1v.x * w, h1v.y * w, h1v.z * w, h1v.w * w);
    *(float4*)(g_acc1 + (size_t)i * 64 + l * 8) = o0;
    *(float4*)(g_acc1 + (size_t)i * 64 + l * 8 + 4) = o1;
}

// ---------------- edge1: single fused scatter pass (layer 1) ----------------
// 8 lanes per edge; lane l = head l (1 scalar RED + 2 v4 REDs per lane).
__global__ __launch_bounds__(256) void edge1_kernel(const void* __restrict__ ei) {
    int t = blockIdx.x * blockDim.x + threadIdx.x;
    int gid = t >> 3, l = t & 7;
    if (gid >= E_EDGES) return;
    int src, dst;
    load_edge(ei, gid, src, dst);
    float e = g_al1s[src * 8 + l] + g_al1d[dst * 8 + l];
    float w = expf(leaky(e));
    atomicAdd(&g_s1[dst * 8 + l], w);
    float4 p0 = *(const float4*)(g_h1 + (size_t)src * 64 + l * 8);
    float4 p1 = *(const float4*)(g_h1 + (size_t)src * 64 + l * 8 + 4);
    red_add_v4(g_acc1 + (size_t)dst * 64 + l * 8, p0.x * w, p0.y * w, p0.z * w, p0.w * w);
    red_add_v4(g_acc1 + (size_t)dst * 64 + l * 8 + 4, p1.x * w, p1.y * w, p1.z * w, p1.w * w);
}

// ---------------- final1: normalize + bias + ELU + GEMM2 + layer-2 attn init ----------------
// 16 lanes per node (lane c = class c); 16 nodes per 256-thread block.
__global__ __launch_bounds__(256) void final1_kernel(const float* __restrict__ W2,
                                                     const float* __restrict__ b1,
                                                     const float* __restrict__ a2s,
                                                     const float* __restrict__ a2d) {
    __shared__ float W2s[64 * 16];
    __shared__ float vbuf[16][64];
    const int tid = threadIdx.x;
    for (int j = tid; j < 64 * 16; j += 256) W2s[j] = W2[j];
    __syncthreads();

    int nl = tid >> 4, c = tid & 15;
    int i = blockIdx.x * 16 + nl;

    if (i < N_NODES) {
        float4 a = *(const float4*)(g_acc1 + (size_t)i * 64 + c * 4);
        float s = g_s1[i * 8 + (c >> 1)];
        float inv = 1.f / s;
        float4 bb = *(const float4*)(b1 + c * 4);
        float v0 = a.x * inv + bb.x;
        float v1 = a.y * inv + bb.y;
        float v2 = a.z * inv + bb.z;
        float v3 = a.w * inv + bb.w;
        // ELU
        v0 = v0 > 0.f ? v0 : expf(v0) - 1.f;
        v1 = v1 > 0.f ? v1 : expf(v1) - 1.f;
        v2 = v2 > 0.f ? v2 : expf(v2) - 1.f;
        v3 = v3 > 0.f ? v3 : expf(v3) - 1.f;
        vbuf[nl][c * 4 + 0] = v0;
        vbuf[nl][c * 4 + 1] = v1;
        vbuf[nl][c * 4 + 2] = v2;
        vbuf[nl][c * 4 + 3] = v3;
    }
    __syncwarp();

    float h2c = 0.f;
    if (i < N_NODES) {
#pragma unroll
        for (int j = 0; j < 64; j++) h2c += vbuf[nl][j] * W2s[j * 16 + c];
    }
    float als = h2c * a2s[c];
    float ald = h2c * a2d[c];
#pragma unroll
    for (int off = 8; off > 0; off >>= 1) {
        als += __shfl_down_sync(0xffffffffu, als, off, 16);
        ald += __shfl_down_sync(0xffffffffu, ald, off, 16);
    }
    als = __shfl_sync(0xffffffffu, als, 0, 16);
    ald = __shfl_sync(0xffffffffu, ald, 0, 16);
    float w = expf(leaky(als + ald));    // self-loop weight, layer 2

    if (i < N_NODES) {
        g_h2[i * 16 + c] = h2c;
        g_acc2[i * 16 + c] = h2c * w;
        if (c == 0) {
            g_al2s[i] = als;
            g_al2d[i] = ald;
            g_s2[i] = w;
        }
    }
}

// ---------------- edge2: fused scatter pass (layer 2), 4 lanes per edge ----------------
__global__ __launch_bounds__(256) void edge2_kernel(const void* __restrict__ ei) {
    int t = blockIdx.x * blockDim.x + threadIdx.x;
    int gid = t >> 2, l = t & 3;
    if (gid >= E_EDGES) return;
    int src, dst;
    load_edge(ei, gid, src, dst);
    float w = expf(leaky(g_al2s[src] + g_al2d[dst]));
    if (l == 0) atomicAdd(&g_s2[dst], w);
    float4 p = *(const float4*)(g_h2 + (size_t)src * 16 + l * 4);
    red_add_v4(g_acc2 + (size_t)dst * 16 + l * 4, p.x * w, p.y * w, p.z * w, p.w * w);
}

// ---------------- final2: normalize + bias + log_softmax ----------------
__global__ __launch_bounds__(256) void final2_kernel(const float* __restrict__ b2,
                                                     float* __restrict__ out) {
    int tid = threadIdx.x;
    int nl = tid >> 4, c = tid & 15;
    int i = blockIdx.x * 16 + nl;
    float o = -1e30f;
    if (i < N_NODES) o = g_acc2[i * 16 + c] / g_s2[i] + b2[c];
    float m = o;
#pragma unroll
    for (int off = 8; off > 0; off >>= 1)
        m = fmaxf(m, __shfl_xor_sync(0xffffffffu, m, off, 16));
    float ex = expf(o - m);
    float sum = ex;
#pragma unroll
    for (int off = 8; off > 0; off >>= 1)
        sum += __shfl_xor_sync(0xffffffffu, sum, off, 16);
    if (i < N_NODES) out[i * 16 + c] = o - m - logf(sum);
}

// ---------------- launch ----------------
extern "C" void kernel_launch(void* const* d_in, const int* in_sizes, int n_in,
                              void* d_out, int out_size) {
    const float* x   = (const float*)d_in[0];
    const void*  ei  = d_in[1];
    const float* W1  = (const float*)d_in[2];
    const float* a1s = (const float*)d_in[3];
    const float* a1d = (const float*)d_in[4];
    const float* b1  = (const float*)d_in[5];
    const float* W2  = (const float*)d_in[6];
    const float* a2s = (const float*)d_in[7];
    const float* a2d = (const float*)d_in[8];
    const float* b2  = (const float*)d_in[9];
    float* out = (float*)d_out;

    detect_kernel<<<1, 256>>>((const int*)ei);
    gemm1_kernel<<<(N_NODES + 127) / 128, 256>>>(x, W1);
    node1_kernel<<<(N_NODES * 8 + 255) / 256, 256>>>(a1s, a1d);
    edge1_kernel<<<(E_EDGES * 8 + 255) / 256, 256>>>(ei);
    final1_kernel<<<(N_NODES + 15) / 16, 256>>>(W2, b1, a2s, a2d);
    edge2_kernel<<<(E_EDGES * 4 + 255) / 256, 256>>>(ei);
    final2_kernel<<<(N_NODES + 15) / 16, 256>>>(b2, out);
}

// round 4
// speedup vs baseline: 1.2232x; 1.2232x over previous
#include <cuda_runtime.h>

#define N_NODES 100000
#define E_EDGES 1600000
#define FIN 512
#define HC1 64
#define H1 8
#define C2 16
#define NEG_SLOPE 0.2f

// ---------------- scratch (static __device__, allocation-free) ----------------
__device__ float g_h1  [(size_t)N_NODES * HC1];   // x @ W1
__device__ float g_al1s[(size_t)N_NODES * H1];
__device__ float g_al1d[(size_t)N_NODES * H1];
__device__ float g_s1  [(size_t)N_NODES * H1];    // softmax denominators (init = self-loop term)
__device__ float g_acc1[(size_t)N_NODES * HC1];   // unnormalized weighted sum
__device__ float g_h2  [(size_t)N_NODES * C2];
__device__ float g_al2s[(size_t)N_NODES];
__device__ float g_al2d[(size_t)N_NODES];
__device__ float g_s2  [(size_t)N_NODES];
__device__ float g_acc2[(size_t)N_NODES * C2];
__device__ int   g_is64;

// vectorized global reduction (sm_90+): 1 instruction adds 4 floats
__device__ __forceinline__ void red_add_v4(float* ptr, float a, float b, float c, float d) {
    asm volatile(
        "{\n\t"
        ".reg .u64 p;\n\t"
        "cvta.to.global.u64 p, %0;\n\t"
        "red.global.add.v4.f32 [p], {%1, %2, %3, %4};\n\t"
        "}"
        :: "l"(ptr), "f"(a), "f"(b), "f"(c), "f"(d) : "memory");
}

__device__ __forceinline__ float leaky(float e) { return e > 0.f ? e : NEG_SLOPE * e; }

__device__ __forceinline__ float to_tf32(float f) {
    unsigned u;
    asm("cvt.rna.tf32.f32 %0, %1;" : "=r"(u) : "f"(f));
    return __uint_as_float(u);
}

// m16n8k8 tf32 mma, row.col, f32 accumulate
__device__ __forceinline__ void mma_tf32(float* d, const float* a, const float* b) {
    asm volatile(
        "mma.sync.aligned.m16n8k8.row.col.f32.tf32.tf32.f32 "
        "{%0,%1,%2,%3}, {%4,%5,%6,%7}, {%8,%9}, {%0,%1,%2,%3};\n"
        : "+f"(d[0]), "+f"(d[1]), "+f"(d[2]), "+f"(d[3])
        : "r"(__float_as_uint(a[0])), "r"(__float_as_uint(a[1])),
          "r"(__float_as_uint(a[2])), "r"(__float_as_uint(a[3])),
          "r"(__float_as_uint(b[0])), "r"(__float_as_uint(b[1])));
}

// ---------------- edge dtype detection (int64 vs int32) ----------------
__global__ void detect_kernel(const int* __restrict__ ei_words) {
    __shared__ int nz;
    if (threadIdx.x == 0) nz = 0;
    __syncthreads();
    for (int i = threadIdx.x; i < 4096; i += blockDim.x)
        if (ei_words[2 * i + 1] != 0) nz = 1;
    __syncthreads();
    if (threadIdx.x == 0) g_is64 = (nz == 0);
}

__device__ __forceinline__ void load_edge(const void* ei, int gid, int& src, int& dst) {
    if (g_is64) {
        const long long* p = (const long long*)ei;
        src = (int)p[gid];
        dst = (int)p[E_EDGES + gid];
    } else {
        const int* p = (const int*)ei;
        src = p[gid];
        dst = p[E_EDGES + gid];
    }
}

// ---------------- GEMM1 (tensor cores, tf32): g_h1 = x @ W1 ----------------
// CTA tile 128x64, BK=32, 8 warps (4x2), each warp 32x32 via m16n8k8 mma.
__global__ __launch_bounds__(256) void gemm1_kernel(const float* __restrict__ x,
                                                    const float* __restrict__ W1) {
    __shared__ float As[128][36];   // pitch 36 -> conflict-free frag loads
    __shared__ float Bs[32][72];    // pitch 72 -> conflict-free frag loads
    const int tid = threadIdx.x;
    const int warp = tid >> 5, lane = tid & 31;
    const int gid = lane >> 2, tig = lane & 3;
    const int mw = (warp >> 1) * 32;     // warp m offset: 0/32/64/96
    const int nw = (warp & 1) * 32;      // warp n offset: 0/32
    const int block_row = blockIdx.x * 128;

    float acc[2][4][4];
#pragma unroll
    for (int mt = 0; mt < 2; mt++)
#pragma unroll
        for (int nt = 0; nt < 4; nt++)
#pragma unroll
            for (int j = 0; j < 4; j++) acc[mt][nt][j] = 0.f;

    for (int k0 = 0; k0 < FIN; k0 += 32) {
        // A tile: 128 rows x 32 k = 1024 float4 -> 4 per thread
#pragma unroll
        for (int p = 0; p < 4; p++) {
            int idx = tid + p * 256;
            int r = idx >> 3, c4 = idx & 7;
            int gr = block_row + r;
            float4 v = make_float4(0.f, 0.f, 0.f, 0.f);
            if (gr < N_NODES)
                v = *(const float4*)(x + (size_t)gr * FIN + k0 + c4 * 4);
            v.x = to_tf32(v.x); v.y = to_tf32(v.y);
            v.z = to_tf32(v.z); v.w = to_tf32(v.w);
            *(float4*)&As[r][c4 * 4] = v;
        }
        // B tile: 32 x 64 = 512 float4 -> 2 per thread
#pragma unroll
        for (int p = 0; p < 2; p++) {
            int idx = tid + p * 256;
            int kk = idx >> 4, n4 = idx & 15;
            float4 v = *(const float4*)(W1 + (size_t)(k0 + kk) * 64 + n4 * 4);
            v.x = to_tf32(v.x); v.y = to_tf32(v.y);
            v.z = to_tf32(v.z); v.w = to_tf32(v.w);
            *(float4*)&Bs[kk][n4 * 4] = v;
        }
        __syncthreads();
#pragma unroll
        for (int kk = 0; kk < 32; kk += 8) {
            float a[2][4];
#pragma unroll
            for (int mt = 0; mt < 2; mt++) {
                int r = mw + mt * 16;
                a[mt][0] = As[r + gid][kk + tig];
                a[mt][1] = As[r + gid + 8][kk + tig];
                a[mt][2] = As[r + gid][kk + tig + 4];
                a[mt][3] = As[r + gid + 8][kk + tig + 4];
            }
            float b[4][2];
#pragma unroll
            for (int nt = 0; nt < 4; nt++) {
                b[nt][0] = Bs[kk + tig][nw + nt * 8 + gid];
                b[nt][1] = Bs[kk + tig + 4][nw + nt * 8 + gid];
            }
#pragma unroll
            for (int mt = 0; mt < 2; mt++)
#pragma unroll
                for (int nt = 0; nt < 4; nt++)
                    mma_tf32(acc[mt][nt], a[mt], b[nt]);
        }
        __syncthreads();
    }

    // epilogue: C frag -> g_h1 (float2 per c-pair)
#pragma unroll
    for (int mt = 0; mt < 2; mt++) {
#pragma unroll
        for (int nt = 0; nt < 4; nt++) {
            int r0 = block_row + mw + mt * 16 + gid;
            int c = nw + nt * 8 + 2 * tig;
            if (r0 < N_NODES)
                *(float2*)(g_h1 + (size_t)r0 * 64 + c) =
                    make_float2(acc[mt][nt][0], acc[mt][nt][1]);
            if (r0 + 8 < N_NODES)
                *(float2*)(g_h1 + (size_t)(r0 + 8) * 64 + c) =
                    make_float2(acc[mt][nt][2], acc[mt][nt][3]);
        }
    }
}

// ---------------- node1: attention logits + self-loop init ----------------
__global__ __launch_bounds__(256) void node1_kernel(const float* __restrict__ a1s,
                                                    const float* __restrict__ a1d) {
    int t = blockIdx.x * blockDim.x + threadIdx.x;
    int i = t >> 3, l = t & 7;
    if (i >= N_NODES) return;
    float4 h0 = *(const float4*)(g_h1 + (size_t)i * 64 + l * 8);
    float4 h1v = *(const float4*)(g_h1 + (size_t)i * 64 + l * 8 + 4);
    const float* as = a1s + l * 8;
    const float* ad = a1d + l * 8;
    float vs = h0.x * as[0] + h0.y * as[1] + h0.z * as[2] + h0.w * as[3] +
               h1v.x * as[4] + h1v.y * as[5] + h1v.z * as[6] + h1v.w * as[7];
    float vd = h0.x * ad[0] + h0.y * ad[1] + h0.z * ad[2] + h0.w * ad[3] +
               h1v.x * ad[4] + h1v.y * ad[5] + h1v.z * ad[6] + h1v.w * ad[7];
    float w = expf(leaky(vs + vd));     // self-loop weight
    g_al1s[i * 8 + l] = vs;
    g_al1d[i * 8 + l] = vd;
    g_s1[i * 8 + l] = w;
    float4 o0 = make_float4(h0.x * w, h0.y * w, h0.z * w, h0.w * w);
    float4 o1 = make_float4(h1v.x * w, h1v.y * w, h1v.z * w, h1v.w * w);
    *(float4*)(g_acc1 + (size_t)i * 64 + l * 8) = o0;
    *(float4*)(g_acc1 + (size_t)i * 64 + l * 8 + 4) = o1;
}

// ---------------- edge1: single fused scatter pass (layer 1) ----------------
// 8 lanes per edge; edge index loaded once per group, broadcast via shfl.
__global__ __launch_bounds__(256) void edge1_kernel(const void* __restrict__ ei) {
    int t = blockIdx.x * blockDim.x + threadIdx.x;
    int gid = t >> 3, l = t & 7;
    int src = 0, dst = 0;
    if (l == 0 && gid < E_EDGES) load_edge(ei, gid, src, dst);
    src = __shfl_sync(0xffffffffu, src, 0, 8);
    dst = __shfl_sync(0xffffffffu, dst, 0, 8);
    if (gid >= E_EDGES) return;
    float e = g_al1s[src * 8 + l] + g_al1d[dst * 8 + l];
    float w = expf(leaky(e));
    atomicAdd(&g_s1[dst * 8 + l], w);
    float4 p0 = *(const float4*)(g_h1 + (size_t)src * 64 + l * 8);
    float4 p1 = *(const float4*)(g_h1 + (size_t)src * 64 + l * 8 + 4);
    red_add_v4(g_acc1 + (size_t)dst * 64 + l * 8, p0.x * w, p0.y * w, p0.z * w, p0.w * w);
    red_add_v4(g_acc1 + (size_t)dst * 64 + l * 8 + 4, p1.x * w, p1.y * w, p1.z * w, p1.w * w);
}

// ---------------- final1: normalize + bias + ELU + GEMM2 + layer-2 attn init ----------------
__global__ __launch_bounds__(256) void final1_kernel(const float* __restrict__ W2,
                                                     const float* __restrict__ b1,
                                                     const float* __restrict__ a2s,
                                                     const float* __restrict__ a2d) {
    __shared__ float W2s[64 * 16];
    __shared__ float vbuf[16][64];
    const int tid = threadIdx.x;
    for (int j = tid; j < 64 * 16; j += 256) W2s[j] = W2[j];
    __syncthreads();

    int nl = tid >> 4, c = tid & 15;
    int i = blockIdx.x * 16 + nl;

    if (i < N_NODES) {
        float4 a = *(const float4*)(g_acc1 + (size_t)i * 64 + c * 4);
        float s = g_s1[i * 8 + (c >> 1)];
        float inv = 1.f / s;
        float4 bb = *(const float4*)(b1 + c * 4);
        float v0 = a.x * inv + bb.x;
        float v1 = a.y * inv + bb.y;
        float v2 = a.z * inv + bb.z;
        float v3 = a.w * inv + bb.w;
        v0 = v0 > 0.f ? v0 : expf(v0) - 1.f;
        v1 = v1 > 0.f ? v1 : expf(v1) - 1.f;
        v2 = v2 > 0.f ? v2 : expf(v2) - 1.f;
        v3 = v3 > 0.f ? v3 : expf(v3) - 1.f;
        vbuf[nl][c * 4 + 0] = v0;
        vbuf[nl][c * 4 + 1] = v1;
        vbuf[nl][c * 4 + 2] = v2;
        vbuf[nl][c * 4 + 3] = v3;
    }
    __syncwarp();

    float h2c = 0.f;
    if (i < N_NODES) {
#pragma unroll
        for (int j = 0; j < 64; j++) h2c += vbuf[nl][j] * W2s[j * 16 + c];
    }
    float als = h2c * a2s[c];
    float ald = h2c * a2d[c];
#pragma unroll
    for (int off = 8; off > 0; off >>= 1) {
        als += __shfl_down_sync(0xffffffffu, als, off, 16);
        ald += __shfl_down_sync(0xffffffffu, ald, off, 16);
    }
    als = __shfl_sync(0xffffffffu, als, 0, 16);
    ald = __shfl_sync(0xffffffffu, ald, 0, 16);
    float w = expf(leaky(als + ald));    // self-loop weight, layer 2

    if (i < N_NODES) {
        g_h2[i * 16 + c] = h2c;
        g_acc2[i * 16 + c] = h2c * w;
        if (c == 0) {
            g_al2s[i] = als;
            g_al2d[i] = ald;
            g_s2[i] = w;
        }
    }
}

// ---------------- edge2: fused scatter pass (layer 2), 4 lanes per edge ----------------
__global__ __launch_bounds__(256) void edge2_kernel(const void* __restrict__ ei) {
    int t = blockIdx.x * blockDim.x + threadIdx.x;
    int gid = t >> 2, l = t & 3;
    int src = 0, dst = 0;
    if (l == 0 && gid < E_EDGES) load_edge(ei, gid, src, dst);
    src = __shfl_sync(0xffffffffu, src, 0, 4);
    dst = __shfl_sync(0xffffffffu, dst, 0, 4);
    if (gid >= E_EDGES) return;
    float w = expf(leaky(g_al2s[src] + g_al2d[dst]));
    if (l == 0) atomicAdd(&g_s2[dst], w);
    float4 p = *(const float4*)(g_h2 + (size_t)src * 16 + l * 4);
    red_add_v4(g_acc2 + (size_t)dst * 16 + l * 4, p.x * w, p.y * w, p.z * w, p.w * w);
}

// ---------------- final2: normalize + bias + log_softmax ----------------
__global__ __launch_bounds__(256) void final2_kernel(const float* __restrict__ b2,
                                                     float* __restrict__ out) {
    int tid = threadIdx.x;
    int nl = tid >> 4, c = tid & 15;
    int i = blockIdx.x * 16 + nl;
    float o = -1e30f;
    if (i < N_NODES) o = g_acc2[i * 16 + c] / g_s2[i] + b2[c];
    float m = o;
#pragma unroll
    for (int off = 8; off > 0; off >>= 1)
        m = fmaxf(m, __shfl_xor_sync(0xffffffffu, m, off, 16));
    float ex = expf(o - m);
    float sum = ex;
#pragma unroll
    for (int off = 8; off > 0; off >>= 1)
        sum += __shfl_xor_sync(0xffffffffu, sum, off, 16);
    if (i < N_NODES) out[i * 16 + c] = o - m - logf(sum);
}

// ---------------- launch ----------------
extern "C" void kernel_launch(void* const* d_in, const int* in_sizes, int n_in,
                              void* d_out, int out_size) {
    const float* x   = (const float*)d_in[0];
    const void*  ei  = d_in[1];
    const float* W1  = (const float*)d_in[2];
    const float* a1s = (const float*)d_in[3];
    const float* a1d = (const float*)d_in[4];
    const float* b1  = (const float*)d_in[5];
    const float* W2  = (const float*)d_in[6];
    const float* a2s = (const float*)d_in[7];
    const float* a2d = (const float*)d_in[8];
    const float* b2  = (const float*)d_in[9];
    float* out = (float*)d_out;

    detect_kernel<<<1, 256>>>((const int*)ei);
    gemm1_kernel<<<(N_NODES + 127) / 128, 256>>>(x, W1);
    node1_kernel<<<(N_NODES * 8 + 255) / 256, 256>>>(a1s, a1d);
    edge1_kernel<<<(E_EDGES * 8 + 255) / 256, 256>>>(ei);
    final1_kernel<<<(N_NODES + 15) / 16, 256>>>(W2, b1, a2s, a2d);
    edge2_kernel<<<(E_EDGES * 4 + 255) / 256, 256>>>(ei);
    final2_kernel<<<(N_NODES + 15) / 16, 256>>>(b2, out);
}

// round 6
// speedup vs baseline: 1.2282x; 1.0042x over previous
#include <cuda_runtime.h>
#include <cuda_fp16.h>

#define N_NODES 100000
#define E_EDGES 1600000
#define FIN 512
#define HC1 64
#define H1 8
#define C2 16
#define NEG_SLOPE 0.2f

// ---------------- scratch (static __device__, allocation-free) ----------------
__device__ float  g_h1  [(size_t)N_NODES * HC1];   // x @ W1 (fp32, for node1/acc init)
__device__ __half g_h1h [(size_t)N_NODES * HC1];   // fp16 copy for edge gather
__device__ float  g_al1s[(size_t)N_NODES * H1];
__device__ float  g_al1d[(size_t)N_NODES * H1];
__device__ float  g_s1  [(size_t)N_NODES * H1];    // softmax denominators (init = self-loop)
__device__ float  g_acc1[(size_t)N_NODES * HC1];   // unnormalized weighted sum (fp32)
__device__ float  g_h2  [(size_t)N_NODES * C2];
__device__ __half g_h2h [(size_t)N_NODES * C2];    // fp16 copy for edge2 gather
__device__ float  g_al2s[(size_t)N_NODES];
__device__ float  g_al2d[(size_t)N_NODES];
__device__ float  g_s2  [(size_t)N_NODES];
__device__ float  g_acc2[(size_t)N_NODES * C2];
__device__ int    g_is64;

// vectorized global reduction (sm_90+): 1 instruction adds 4 floats
__device__ __forceinline__ void red_add_v4(float* ptr, float a, float b, float c, float d) {
    asm volatile(
        "{\n\t"
        ".reg .u64 p;\n\t"
        "cvta.to.global.u64 p, %0;\n\t"
        "red.global.add.v4.f32 [p], {%1, %2, %3, %4};\n\t"
        "}"
        :: "l"(ptr), "f"(a), "f"(b), "f"(c), "f"(d) : "memory");
}

__device__ __forceinline__ float leaky(float e) { return e > 0.f ? e : NEG_SLOPE * e; }

__device__ __forceinline__ float to_tf32(float f) {
    unsigned u;
    asm("cvt.rna.tf32.f32 %0, %1;" : "=r"(u) : "f"(f));
    return __uint_as_float(u);
}

// m16n8k8 tf32 mma, row.col, f32 accumulate
__device__ __forceinline__ void mma_tf32(float* d, const float* a, const float* b) {
    asm volatile(
        "mma.sync.aligned.m16n8k8.row.col.f32.tf32.tf32.f32 "
        "{%0,%1,%2,%3}, {%4,%5,%6,%7}, {%8,%9}, {%0,%1,%2,%3};\n"
        : "+f"(d[0]), "+f"(d[1]), "+f"(d[2]), "+f"(d[3])
        : "r"(__float_as_uint(a[0])), "r"(__float_as_uint(a[1])),
          "r"(__float_as_uint(a[2])), "r"(__float_as_uint(a[3])),
          "r"(__float_as_uint(b[0])), "r"(__float_as_uint(b[1])));
}

// ---------------- edge dtype detection (int64 vs int32) ----------------
__global__ void detect_kernel(const int* __restrict__ ei_words) {
    __shared__ int nz;
    if (threadIdx.x == 0) nz = 0;
    __syncthreads();
    for (int i = threadIdx.x; i < 4096; i += blockDim.x)
        if (ei_words[2 * i + 1] != 0) nz = 1;
    __syncthreads();
    if (threadIdx.x == 0) g_is64 = (nz == 0);
}

__device__ __forceinline__ void load_edge(const void* ei, int gid, int& src, int& dst) {
    if (g_is64) {
        const long long* p = (const long long*)ei;
        src = (int)p[gid];
        dst = (int)p[E_EDGES + gid];
    } else {
        const int* p = (const int*)ei;
        src = p[gid];
        dst = p[E_EDGES + gid];
    }
}

// ---------------- GEMM1 (tensor cores, tf32): g_h1 = x @ W1 ----------------
// CTA tile 128x64, BK=32, 8 warps (4x2), each warp 32x32 via m16n8k8 mma.
// Epilogue writes fp32 copy + fp16 copy (for edge gather).
__global__ __launch_bounds__(256) void gemm1_kernel(const float* __restrict__ x,
                                                    const float* __restrict__ W1) {
    __shared__ float As[128][36];   // pitch 36 -> conflict-free frag loads
    __shared__ float Bs[32][72];    // pitch 72 -> conflict-free frag loads
    const int tid = threadIdx.x;
    const int warp = tid >> 5, lane = tid & 31;
    const int gid = lane >> 2, tig = lane & 3;
    const int mw = (warp >> 1) * 32;     // warp m offset: 0/32/64/96
    const int nw = (warp & 1) * 32;      // warp n offset: 0/32
    const int block_row = blockIdx.x * 128;

    float acc[2][4][4];
#pragma unroll
    for (int mt = 0; mt < 2; mt++)
#pragma unroll
        for (int nt = 0; nt < 4; nt++)
#pragma unroll
            for (int j = 0; j < 4; j++) acc[mt][nt][j] = 0.f;

    for (int k0 = 0; k0 < FIN; k0 += 32) {
        // A tile: 128 rows x 32 k = 1024 float4 -> 4 per thread
#pragma unroll
        for (int p = 0; p < 4; p++) {
            int idx = tid + p * 256;
            int r = idx >> 3, c4 = idx & 7;
            int gr = block_row + r;
            float4 v = make_float4(0.f, 0.f, 0.f, 0.f);
            if (gr < N_NODES)
                v = *(const float4*)(x + (size_t)gr * FIN + k0 + c4 * 4);
            v.x = to_tf32(v.x); v.y = to_tf32(v.y);
            v.z = to_tf32(v.z); v.w = to_tf32(v.w);
            *(float4*)&As[r][c4 * 4] = v;
        }
        // B tile: 32 x 64 = 512 float4 -> 2 per thread
#pragma unroll
        for (int p = 0; p < 2; p++) {
            int idx = tid + p * 256;
            int kk = idx >> 4, n4 = idx & 15;
            float4 v = *(const float4*)(W1 + (size_t)(k0 + kk) * 64 + n4 * 4);
            v.x = to_tf32(v.x); v.y = to_tf32(v.y);
            v.z = to_tf32(v.z); v.w = to_tf32(v.w);
            *(float4*)&Bs[kk][n4 * 4] = v;
        }
        __syncthreads();
#pragma unroll
        for (int kk = 0; kk < 32; kk += 8) {
            float a[2][4];
#pragma unroll
            for (int mt = 0; mt < 2; mt++) {
                int r = mw + mt * 16;
                a[mt][0] = As[r + gid][kk + tig];
                a[mt][1] = As[r + gid + 8][kk + tig];
                a[mt][2] = As[r + gid][kk + tig + 4];
                a[mt][3] = As[r + gid + 8][kk + tig + 4];
            }
            float b[4][2];
#pragma unroll
            for (int nt = 0; nt < 4; nt++) {
                b[nt][0] = Bs[kk + tig][nw + nt * 8 + gid];
                b[nt][1] = Bs[kk + tig + 4][nw + nt * 8 + gid];
            }
#pragma unroll
            for (int mt = 0; mt < 2; mt++)
#pragma unroll
                for (int nt = 0; nt < 4; nt++)
                    mma_tf32(acc[mt][nt], a[mt], b[nt]);
        }
        __syncthreads();
    }

    // epilogue: C frag -> g_h1 (fp32) + g_h1h (fp16)
#pragma unroll
    for (int mt = 0; mt < 2; mt++) {
#pragma unroll
        for (int nt = 0; nt < 4; nt++) {
            int r0 = block_row + mw + mt * 16 + gid;
            int c = nw + nt * 8 + 2 * tig;
            if (r0 < N_NODES) {
                *(float2*)(g_h1 + (size_t)r0 * 64 + c) =
                    make_float2(acc[mt][nt][0], acc[mt][nt][1]);
                *(__half2*)(g_h1h + (size_t)r0 * 64 + c) =
                    __floats2half2_rn(acc[mt][nt][0], acc[mt][nt][1]);
            }
            if (r0 + 8 < N_NODES) {
                *(float2*)(g_h1 + (size_t)(r0 + 8) * 64 + c) =
                    make_float2(acc[mt][nt][2], acc[mt][nt][3]);
                *(__half2*)(g_h1h + (size_t)(r0 + 8) * 64 + c) =
                    __floats2half2_rn(acc[mt][nt][2], acc[mt][nt][3]);
            }
        }
    }
}

// ---------------- node1: attention logits + self-loop init ----------------
__global__ __launch_bounds__(256) void node1_kernel(const float* __restrict__ a1s,
                                                    const float* __restrict__ a1d) {
    int t = blockIdx.x * blockDim.x + threadIdx.x;
    int i = t >> 3, l = t & 7;
    if (i >= N_NODES) return;
    float4 h0 = *(const float4*)(g_h1 + (size_t)i * 64 + l * 8);
    float4 h1v = *(const float4*)(g_h1 + (size_t)i * 64 + l * 8 + 4);
    const float* as = a1s + l * 8;
    const float* ad = a1d + l * 8;
    float vs = h0.x * as[0] + h0.y * as[1] + h0.z * as[2] + h0.w * as[3] +
               h1v.x * as[4] + h1v.y * as[5] + h1v.z * as[6] + h1v.w * as[7];
    float vd = h0.x * ad[0] + h0.y * ad[1] + h0.z * ad[2] + h0.w * ad[3] +
               h1v.x * ad[4] + h1v.y * ad[5] + h1v.z * ad[6] + h1v.w * ad[7];
    float w = expf(leaky(vs + vd));     // self-loop weight
    g_al1s[i * 8 + l] = vs;
    g_al1d[i * 8 + l] = vd;
    g_s1[i * 8 + l] = w;
    float4 o0 = make_float4(h0.x * w, h0.y * w, h0.z * w, h0.w * w);
    float4 o1 = make_float4(h1v.x * w, h1v.y * w, h1v.z * w, h1v.w * w);
    *(float4*)(g_acc1 + (size_t)i * 64 + l * 8) = o0;
    *(float4*)(g_acc1 + (size_t)i * 64 + l * 8 + 4) = o1;
}

// ---------------- edge1: single fused scatter pass (layer 1) ----------------
// 8 lanes per edge; gather fp16 h1 (1 LDG.128/lane), accumulate fp32 via RED.
__global__ __launch_bounds__(256) void edge1_kernel(const void* __restrict__ ei) {
    int t = blockIdx.x * blockDim.x + threadIdx.x;
    int gid = t >> 3, l = t & 7;
    if (gid >= E_EDGES) return;
    int src, dst;
    load_edge(ei, gid, src, dst);
    float e = g_al1s[src * 8 + l] + g_al1d[dst * 8 + l];
    float w = expf(leaky(e));
    atomicAdd(&g_s1[dst * 8 + l], w);
    // fp16 gather: 8 halves = 16B = one uint4
    uint4 hv = *(const uint4*)(g_h1h + (size_t)src * 64 + l * 8);
    float2 f0 = __half22float2(*(__half2*)&hv.x);
    float2 f1 = __half22float2(*(__half2*)&hv.y);
    float2 f2 = __half22float2(*(__half2*)&hv.z);
    float2 f3 = __half22float2(*(__half2*)&hv.w);
    red_add_v4(g_acc1 + (size_t)dst * 64 + l * 8,
               f0.x * w, f0.y * w, f1.x * w, f1.y * w);
    red_add_v4(g_acc1 + (size_t)dst * 64 + l * 8 + 4,
               f2.x * w, f2.y * w, f3.x * w, f3.y * w);
}

// ---------------- final1: normalize + bias + ELU + GEMM2 + layer-2 attn init ----------------
__global__ __launch_bounds__(256) void final1_kernel(const float* __restrict__ W2,
                                                     const float* __restrict__ b1,
                                                     const float* __restrict__ a2s,
                                                     const float* __restrict__ a2d) {
    __shared__ float W2s[64 * 16];
    __shared__ float vbuf[16][64];
    const int tid = threadIdx.x;
    for (int j = tid; j < 64 * 16; j += 256) W2s[j] = W2[j];
    __syncthreads();

    int nl = tid >> 4, c = tid & 15;
    int i = blockIdx.x * 16 + nl;

    if (i < N_NODES) {
        float4 a = *(const float4*)(g_acc1 + (size_t)i * 64 + c * 4);
        float s = g_s1[i * 8 + (c >> 1)];
        float inv = 1.f / s;
        float4 bb = *(const float4*)(b1 + c * 4);
        float v0 = a.x * inv + bb.x;
        float v1 = a.y * inv + bb.y;
        float v2 = a.z * inv + bb.z;
        float v3 = a.w * inv + bb.w;
        v0 = v0 > 0.f ? v0 : expf(v0) - 1.f;
        v1 = v1 > 0.f ? v1 : expf(v1) - 1.f;
        v2 = v2 > 0.f ? v2 : expf(v2) - 1.f;
        v3 = v3 > 0.f ? v3 : expf(v3) - 1.f;
        vbuf[nl][c * 4 + 0] = v0;
        vbuf[nl][c * 4 + 1] = v1;
        vbuf[nl][c * 4 + 2] = v2;
        vbuf[nl][c * 4 + 3] = v3;
    }
    __syncwarp();

    float h2c = 0.f;
    if (i < N_NODES) {
#pragma unroll
        for (int j = 0; j < 64; j++) h2c += vbuf[nl][j] * W2s[j * 16 + c];
    }
    float als = h2c * a2s[c];
    float ald = h2c * a2d[c];
#pragma unroll
    for (int off = 8; off > 0; off >>= 1) {
        als += __shfl_down_sync(0xffffffffu, als, off, 16);
        ald += __shfl_down_sync(0xffffffffu, ald, off, 16);
    }
    als = __shfl_sync(0xffffffffu, als, 0, 16);
    ald = __shfl_sync(0xffffffffu, ald, 0, 16);
    float w = expf(leaky(als + ald));    // self-loop weight, layer 2

    if (i < N_NODES) {
        g_h2[i * 16 + c] = h2c;
        g_h2h[i * 16 + c] = __float2half_rn(h2c);
        g_acc2[i * 16 + c] = h2c * w;
        if (c == 0) {
            g_al2s[i] = als;
            g_al2d[i] = ald;
            g_s2[i] = w;
        }
    }
}

// ---------------- edge2: fused scatter pass (layer 2), 4 lanes per edge ----------------
// fp16 gather of h2 (1 LDG.64/lane), fp32 RED accumulate.
__global__ __launch_bounds__(256) void edge2_kernel(const void* __restrict__ ei) {
    int t = blockIdx.x * blockDim.x + threadIdx.x;
    int gid = t >> 2, l = t & 3;
    if (gid >= E_EDGES) return;
    int src, dst;
    load_edge(ei, gid, src, dst);
    float w = expf(leaky(g_al2s[src] + g_al2d[dst]));
    if (l == 0) atomicAdd(&g_s2[dst], w);
    uint2 hv = *(const uint2*)(g_h2h + (size_t)src * 16 + l * 4);
    float2 f0 = __half22float2(*(__half2*)&hv.x);
    float2 f1 = __half22float2(*(__half2*)&hv.y);
    red_add_v4(g_acc2 + (size_t)dst * 16 + l * 4,
               f0.x * w, f0.y * w, f1.x * w, f1.y * w);
}

// ---------------- final2: normalize + bias + log_softmax ----------------
__global__ __launch_bounds__(256) void final2_kernel(const float* __restrict__ b2,
                                                     float* __restrict__ out) {
    int tid = threadIdx.x;
    int nl = tid >> 4, c = tid & 15;
    int i = blockIdx.x * 16 + nl;
    float o = -1e30f;
    if (i < N_NODES) o = g_acc2[i * 16 + c] / g_s2[i] + b2[c];
    float m = o;
#pragma unroll
    for (int off = 8; off > 0; off >>= 1)
        m = fmaxf(m, __shfl_xor_sync(0xffffffffu, m, off, 16));
    float ex = expf(o - m);
    float sum = ex;
#pragma unroll
    for (int off = 8; off > 0; off >>= 1)
        sum += __shfl_xor_sync(0xffffffffu, sum, off, 16);
    if (i < N_NODES) out[i * 16 + c] = o - m - logf(sum);
}

// ---------------- launch ----------------
extern "C" void kernel_launch(void* const* d_in, const int* in_sizes, int n_in,
                              void* d_out, int out_size) {
    const float* x   = (const float*)d_in[0];
    const void*  ei  = d_in[1];
    const float* W1  = (const float*)d_in[2];
    const float* a1s = (const float*)d_in[3];
    const float* a1d = (const float*)d_in[4];
    const float* b1  = (const float*)d_in[5];
    const float* W2  = (const float*)d_in[6];
    const float* a2s = (const float*)d_in[7];
    const float* a2d = (const float*)d_in[8];
    const float* b2  = (const float*)d_in[9];
    float* out = (float*)d_out;

    detect_kernel<<<1, 256>>>((const int*)ei);
    gemm1_kernel<<<(N_NODES + 127) / 128, 256>>>(x, W1);
    node1_kernel<<<(N_NODES * 8 + 255) / 256, 256>>>(a1s, a1d);
    edge1_kernel<<<(E_EDGES * 8 + 255) / 256, 256>>>(ei);
    final1_kernel<<<(N_NODES + 15) / 16, 256>>>(W2, b1, a2s, a2d);
    edge2_kernel<<<(E_EDGES * 4 + 255) / 256, 256>>>(ei);
    final2_kernel<<<(N_NODES + 15) / 16, 256>>>(b2, out);
}

// round 7
// speedup vs baseline: 1.4596x; 1.1883x over previous
#include <cuda_runtime.h>
#include <cuda_fp16.h>

#define N_NODES 100000
#define E_EDGES 1600000
#define FIN 512
#define HC1 64
#define H1 8
#define C2 16
#define NEG_SLOPE 0.2f
#define SCAN_NB ((N_NODES + 1023) / 1024)

// ---------------- scratch (static __device__, allocation-free) ----------------
__device__ float  g_h1  [(size_t)N_NODES * HC1];   // x @ W1 (fp32)
__device__ __half g_h1h [(size_t)N_NODES * HC1];   // fp16 copy for edge gather
__device__ float  g_al1s[(size_t)N_NODES * H1];
__device__ float  g_al1d[(size_t)N_NODES * H1];
__device__ float  g_acc1[(size_t)N_NODES * HC1];   // NORMALIZED layer-1 aggregate
__device__ __half g_h2h [(size_t)N_NODES * C2];    // fp16 h2 for edge2 gather
__device__ float  g_al2s[(size_t)N_NODES];
__device__ float  g_al2d[(size_t)N_NODES];
__device__ float  g_acc2[(size_t)N_NODES * C2];    // NORMALIZED layer-2 aggregate
__device__ int    g_is64;

// CSR build scratch
__device__ int g_cnt      [N_NODES];
__device__ int g_incl     [N_NODES];
__device__ int g_part     [SCAN_NB + 1];
__device__ int g_row_start[N_NODES];
__device__ int g_row_end  [N_NODES];
__device__ int g_cursor   [N_NODES];
__device__ int g_csr_src  [E_EDGES];

__device__ __forceinline__ float leaky(float e) { return e > 0.f ? e : NEG_SLOPE * e; }

__device__ __forceinline__ float to_tf32(float f) {
    unsigned u;
    asm("cvt.rna.tf32.f32 %0, %1;" : "=r"(u) : "f"(f));
    return __uint_as_float(u);
}

// m16n8k8 tf32 mma, row.col, f32 accumulate
__device__ __forceinline__ void mma_tf32(float* d, const float* a, const float* b) {
    asm volatile(
        "mma.sync.aligned.m16n8k8.row.col.f32.tf32.tf32.f32 "
        "{%0,%1,%2,%3}, {%4,%5,%6,%7}, {%8,%9}, {%0,%1,%2,%3};\n"
        : "+f"(d[0]), "+f"(d[1]), "+f"(d[2]), "+f"(d[3])
        : "r"(__float_as_uint(a[0])), "r"(__float_as_uint(a[1])),
          "r"(__float_as_uint(a[2])), "r"(__float_as_uint(a[3])),
          "r"(__float_as_uint(b[0])), "r"(__float_as_uint(b[1])));
}

// ---------------- edge dtype detection (int64 vs int32) ----------------
__global__ void detect_kernel(const int* __restrict__ ei_words) {
    __shared__ int nz;
    if (threadIdx.x == 0) nz = 0;
    __syncthreads();
    for (int i = threadIdx.x; i < 4096; i += blockDim.x)
        if (ei_words[2 * i + 1] != 0) nz = 1;
    __syncthreads();
    if (threadIdx.x == 0) g_is64 = (nz == 0);
}

__device__ __forceinline__ void load_edge(const void* ei, int gid, int& src, int& dst) {
    if (g_is64) {
        const long long* p = (const long long*)ei;
        src = (int)p[gid];
        dst = (int)p[E_EDGES + gid];
    } else {
        const int* p = (const int*)ei;
        src = p[gid];
        dst = p[E_EDGES + gid];
    }
}

__device__ __forceinline__ int load_dst(const void* ei, int gid) {
    if (g_is64) return (int)((const long long*)ei)[E_EDGES + gid];
    return ((const int*)ei)[E_EDGES + gid];
}

// ---------------- CSR build ----------------
__global__ void zero_kernel() {
    int i = blockIdx.x * blockDim.x + threadIdx.x;
    if (i < N_NODES) g_cnt[i] = 0;
}

__global__ void hist_kernel(const void* __restrict__ ei) {
    int gid = blockIdx.x * blockDim.x + threadIdx.x;
    if (gid >= E_EDGES) return;
    atomicAdd(&g_cnt[load_dst(ei, gid)], 1);
}

__global__ __launch_bounds__(1024) void scan1_kernel() {
    __shared__ int sm[1024];
    int i = blockIdx.x * 1024 + threadIdx.x;
    sm[threadIdx.x] = (i < N_NODES) ? g_cnt[i] : 0;
    __syncthreads();
#pragma unroll
    for (int off = 1; off < 1024; off <<= 1) {
        int t = (threadIdx.x >= off) ? sm[threadIdx.x - off] : 0;
        __syncthreads();
        sm[threadIdx.x] += t;
        __syncthreads();
    }
    if (i < N_NODES) g_incl[i] = sm[threadIdx.x];
    if (threadIdx.x == 1023) g_part[blockIdx.x] = sm[1023];
}

__global__ void scan2_kernel() {
    if (threadIdx.x == 0) {
        int s = 0;
        for (int b = 0; b < SCAN_NB; b++) {
            int t = g_part[b];
            g_part[b] = s;
            s += t;
        }
    }
}

__global__ void scan3_kernel() {
    int i = blockIdx.x * blockDim.x + threadIdx.x;
    if (i >= N_NODES) return;
    int inc = g_incl[i] + g_part[i >> 10];
    int c = g_cnt[i];
    g_row_start[i] = inc - c;
    g_row_end[i] = inc;
    g_cursor[i] = inc - c;
}

__global__ void scatter_kernel(const void* __restrict__ ei) {
    int gid = blockIdx.x * blockDim.x + threadIdx.x;
    if (gid >= E_EDGES) return;
    int src, dst;
    load_edge(ei, gid, src, dst);
    int pos = atomicAdd(&g_cursor[dst], 1);
    g_csr_src[pos] = src;
}

// ---------------- GEMM1 (tensor cores, tf32): g_h1 = x @ W1 ----------------
__global__ __launch_bounds__(256) void gemm1_kernel(const float* __restrict__ x,
                                                    const float* __restrict__ W1) {
    __shared__ float As[128][36];
    __shared__ float Bs[32][72];
    const int tid = threadIdx.x;
    const int warp = tid >> 5, lane = tid & 31;
    const int gid = lane >> 2, tig = lane & 3;
    const int mw = (warp >> 1) * 32;
    const int nw = (warp & 1) * 32;
    const int block_row = blockIdx.x * 128;

    float acc[2][4][4];
#pragma unroll
    for (int mt = 0; mt < 2; mt++)
#pragma unroll
        for (int nt = 0; nt < 4; nt++)
#pragma unroll
            for (int j = 0; j < 4; j++) acc[mt][nt][j] = 0.f;

    for (int k0 = 0; k0 < FIN; k0 += 32) {
#pragma unroll
        for (int p = 0; p < 4; p++) {
            int idx = tid + p * 256;
            int r = idx >> 3, c4 = idx & 7;
            int gr = block_row + r;
            float4 v = make_float4(0.f, 0.f, 0.f, 0.f);
            if (gr < N_NODES)
                v = *(const float4*)(x + (size_t)gr * FIN + k0 + c4 * 4);
            v.x = to_tf32(v.x); v.y = to_tf32(v.y);
            v.z = to_tf32(v.z); v.w = to_tf32(v.w);
            *(float4*)&As[r][c4 * 4] = v;
        }
#pragma unroll
        for (int p = 0; p < 2; p++) {
            int idx = tid + p * 256;
            int kk = idx >> 4, n4 = idx & 15;
            float4 v = *(const float4*)(W1 + (size_t)(k0 + kk) * 64 + n4 * 4);
            v.x = to_tf32(v.x); v.y = to_tf32(v.y);
            v.z = to_tf32(v.z); v.w = to_tf32(v.w);
            *(float4*)&Bs[kk][n4 * 4] = v;
        }
        __syncthreads();
#pragma unroll
        for (int kk = 0; kk < 32; kk += 8) {
            float a[2][4];
#pragma unroll
            for (int mt = 0; mt < 2; mt++) {
                int r = mw + mt * 16;
                a[mt][0] = As[r + gid][kk + tig];
                a[mt][1] = As[r + gid + 8][kk + tig];
                a[mt][2] = As[r + gid][kk + tig + 4];
                a[mt][3] = As[r + gid + 8][kk + tig + 4];
            }
            float b[4][2];
#pragma unroll
            for (int nt = 0; nt < 4; nt++) {
                b[nt][0] = Bs[kk + tig][nw + nt * 8 + gid];
                b[nt][1] = Bs[kk + tig + 4][nw + nt * 8 + gid];
            }
#pragma unroll
            for (int mt = 0; mt < 2; mt++)
#pragma unroll
                for (int nt = 0; nt < 4; nt++)
                    mma_tf32(acc[mt][nt], a[mt], b[nt]);
        }
        __syncthreads();
    }

#pragma unroll
    for (int mt = 0; mt < 2; mt++) {
#pragma unroll
        for (int nt = 0; nt < 4; nt++) {
            int r0 = block_row + mw + mt * 16 + gid;
            int c = nw + nt * 8 + 2 * tig;
            if (r0 < N_NODES) {
                *(float2*)(g_h1 + (size_t)r0 * 64 + c) =
                    make_float2(acc[mt][nt][0], acc[mt][nt][1]);
                *(__half2*)(g_h1h + (size_t)r0 * 64 + c) =
                    __floats2half2_rn(acc[mt][nt][0], acc[mt][nt][1]);
            }
            if (r0 + 8 < N_NODES) {
                *(float2*)(g_h1 + (size_t)(r0 + 8) * 64 + c) =
                    make_float2(acc[mt][nt][2], acc[mt][nt][3]);
                *(__half2*)(g_h1h + (size_t)(r0 + 8) * 64 + c) =
                    __floats2half2_rn(acc[mt][nt][2], acc[mt][nt][3]);
            }
        }
    }
}

// ---------------- node1: attention logits only ----------------
__global__ __launch_bounds__(256) void node1_kernel(const float* __restrict__ a1s,
                                                    const float* __restrict__ a1d) {
    int t = blockIdx.x * blockDim.x + threadIdx.x;
    int i = t >> 3, l = t & 7;
    if (i >= N_NODES) return;
    float4 h0 = *(const float4*)(g_h1 + (size_t)i * 64 + l * 8);
    float4 h1v = *(const float4*)(g_h1 + (size_t)i * 64 + l * 8 + 4);
    const float* as = a1s + l * 8;
    const float* ad = a1d + l * 8;
    float vs = h0.x * as[0] + h0.y * as[1] + h0.z * as[2] + h0.w * as[3] +
               h1v.x * as[4] + h1v.y * as[5] + h1v.z * as[6] + h1v.w * as[7];
    float vd = h0.x * ad[0] + h0.y * ad[1] + h0.z * ad[2] + h0.w * ad[3] +
               h1v.x * ad[4] + h1v.y * ad[5] + h1v.z * ad[6] + h1v.w * ad[7];
    g_al1s[i * 8 + l] = vs;
    g_al1d[i * 8 + l] = vd;
}

// ---------------- edge1 (CSR pull): one warp per dst node ----------------
// 8 lanes per edge (lane&7 = head), 4 edges in flight. Register accumulation,
// shfl reduction, normalized single write. Zero atomics.
__global__ __launch_bounds__(256) void edge1_csr_kernel() {
    int w = (blockIdx.x * blockDim.x + threadIdx.x) >> 5;
    if (w >= N_NODES) return;
    const int lane = threadIdx.x & 31;
    const int sub = lane >> 3, l = lane & 7;
    const int i = w;

    float ald = g_al1d[i * 8 + l];
    float acc[8];
#pragma unroll
    for (int j = 0; j < 8; j++) acc[j] = 0.f;
    float wsum = 0.f;

    if (sub == 0) {  // self-loop
        float e = g_al1s[i * 8 + l] + ald;
        float ws = expf(leaky(e));
        wsum = ws;
        uint4 hv = *(const uint4*)(g_h1h + (size_t)i * 64 + l * 8);
        float2 f0 = __half22float2(*(__half2*)&hv.x);
        float2 f1 = __half22float2(*(__half2*)&hv.y);
        float2 f2 = __half22float2(*(__half2*)&hv.z);
        float2 f3 = __half22float2(*(__half2*)&hv.w);
        acc[0] = ws * f0.x; acc[1] = ws * f0.y;
        acc[2] = ws * f1.x; acc[3] = ws * f1.y;
        acc[4] = ws * f2.x; acc[5] = ws * f2.y;
        acc[6] = ws * f3.x; acc[7] = ws * f3.y;
    }

    const int start = g_row_start[i], end = g_row_end[i];
    for (int p = start + sub; p < end; p += 4) {
        int src = g_csr_src[p];
        float e = g_al1s[src * 8 + l] + ald;
        float wv = expf(leaky(e));
        wsum += wv;
        uint4 hv = *(const uint4*)(g_h1h + (size_t)src * 64 + l * 8);
        float2 f0 = __half22float2(*(__half2*)&hv.x);
        float2 f1 = __half22float2(*(__half2*)&hv.y);
        float2 f2 = __half22float2(*(__half2*)&hv.z);
        float2 f3 = __half22float2(*(__half2*)&hv.w);
        acc[0] += wv * f0.x; acc[1] += wv * f0.y;
        acc[2] += wv * f1.x; acc[3] += wv * f1.y;
        acc[4] += wv * f2.x; acc[5] += wv * f2.y;
        acc[6] += wv * f3.x; acc[7] += wv * f3.y;
    }

#pragma unroll
    for (int off = 8; off <= 16; off <<= 1) {
        wsum += __shfl_xor_sync(0xffffffffu, wsum, off);
#pragma unroll
        for (int j = 0; j < 8; j++)
            acc[j] += __shfl_xor_sync(0xffffffffu, acc[j], off);
    }

    if (sub == 0) {
        float inv = 1.f / wsum;
        *(float4*)(g_acc1 + (size_t)i * 64 + l * 8) =
            make_float4(acc[0] * inv, acc[1] * inv, acc[2] * inv, acc[3] * inv);
        *(float4*)(g_acc1 + (size_t)i * 64 + l * 8 + 4) =
            make_float4(acc[4] * inv, acc[5] * inv, acc[6] * inv, acc[7] * inv);
    }
}

// ---------------- final1: bias + ELU + GEMM2 + layer-2 attn logits ----------------
__global__ __launch_bounds__(256) void final1_kernel(const float* __restrict__ W2,
                                                     const float* __restrict__ b1,
                                                     const float* __restrict__ a2s,
                                                     const float* __restrict__ a2d) {
    __shared__ float W2s[64 * 16];
    __shared__ float vbuf[16][64];
    const int tid = threadIdx.x;
    for (int j = tid; j < 64 * 16; j += 256) W2s[j] = W2[j];
    __syncthreads();

    int nl = tid >> 4, c = tid & 15;
    int i = blockIdx.x * 16 + nl;

    if (i < N_NODES) {
        float4 a = *(const float4*)(g_acc1 + (size_t)i * 64 + c * 4);  // already normalized
        float4 bb = *(const float4*)(b1 + c * 4);
        float v0 = a.x + bb.x;
        float v1 = a.y + bb.y;
        float v2 = a.z + bb.z;
        float v3 = a.w + bb.w;
        v0 = v0 > 0.f ? v0 : expf(v0) - 1.f;
        v1 = v1 > 0.f ? v1 : expf(v1) - 1.f;
        v2 = v2 > 0.f ? v2 : expf(v2) - 1.f;
        v3 = v3 > 0.f ? v3 : expf(v3) - 1.f;
        vbuf[nl][c * 4 + 0] = v0;
        vbuf[nl][c * 4 + 1] = v1;
        vbuf[nl][c * 4 + 2] = v2;
        vbuf[nl][c * 4 + 3] = v3;
    }
    __syncwarp();

    float h2c = 0.f;
    if (i < N_NODES) {
#pragma unroll
        for (int j = 0; j < 64; j++) h2c += vbuf[nl][j] * W2s[j * 16 + c];
    }
    float als = h2c * a2s[c];
    float ald = h2c * a2d[c];
#pragma unroll
    for (int off = 8; off > 0; off >>= 1) {
        als += __shfl_down_sync(0xffffffffu, als, off, 16);
        ald += __shfl_down_sync(0xffffffffu, ald, off, 16);
    }
    als = __shfl_sync(0xffffffffu, als, 0, 16);
    ald = __shfl_sync(0xffffffffu, ald, 0, 16);

    if (i < N_NODES) {
        g_h2h[i * 16 + c] = __float2half_rn(h2c);
        if (c == 0) {
            g_al2s[i] = als;
            g_al2d[i] = ald;
        }
    }
}

// ---------------- edge2 (CSR pull): one warp per dst node ----------------
// 4 lanes per edge (lane&3 = channel quad), 8 edges in flight.
__global__ __launch_bounds__(256) void edge2_csr_kernel() {
    int w = (blockIdx.x * blockDim.x + threadIdx.x) >> 5;
    if (w >= N_NODES) return;
    const int lane = threadIdx.x & 31;
    const int sub = lane >> 2, l = lane & 3;
    const int i = w;

    float ald = g_al2d[i];
    float acc[4];
#pragma unroll
    for (int j = 0; j < 4; j++) acc[j] = 0.f;
    float wsum = 0.f;

    if (sub == 0) {  // self-loop
        float ws = expf(leaky(g_al2s[i] + ald));
        wsum = ws;
        uint2 hv = *(const uint2*)(g_h2h + (size_t)i * 16 + l * 4);
        float2 f0 = __half22float2(*(__half2*)&hv.x);
        float2 f1 = __half22float2(*(__half2*)&hv.y);
        acc[0] = ws * f0.x; acc[1] = ws * f0.y;
        acc[2] = ws * f1.x; acc[3] = ws * f1.y;
    }

    const int start = g_row_start[i], end = g_row_end[i];
    for (int p = start + sub; p < end; p += 8) {
        int src = g_csr_src[p];
        float wv = expf(leaky(g_al2s[src] + ald));
        wsum += wv;
        uint2 hv = *(const uint2*)(g_h2h + (size_t)src * 16 + l * 4);
        float2 f0 = __half22float2(*(__half2*)&hv.x);
        float2 f1 = __half22float2(*(__half2*)&hv.y);
        acc[0] += wv * f0.x; acc[1] += wv * f0.y;
        acc[2] += wv * f1.x; acc[3] += wv * f1.y;
    }

#pragma unroll
    for (int off = 4; off <= 16; off <<= 1) {
        wsum += __shfl_xor_sync(0xffffffffu, wsum, off);
#pragma unroll
        for (int j = 0; j < 4; j++)
            acc[j] += __shfl_xor_sync(0xffffffffu, acc[j], off);
    }

    if (sub == 0) {
        float inv = 1.f / wsum;
        *(float4*)(g_acc2 + (size_t)i * 16 + l * 4) =
            make_float4(acc[0] * inv, acc[1] * inv, acc[2] * inv, acc[3] * inv);
    }
}

// ---------------- final2: bias + log_softmax ----------------
__global__ __launch_bounds__(256) void final2_kernel(const float* __restrict__ b2,
                                                     float* __restrict__ out) {
    int tid = threadIdx.x;
    int nl = tid >> 4, c = tid & 15;
    int i = blockIdx.x * 16 + nl;
    float o = -1e30f;
    if (i < N_NODES) o = g_acc2[i * 16 + c] + b2[c];
    float m = o;
#pragma unroll
    for (int off = 8; off > 0; off >>= 1)
        m = fmaxf(m, __shfl_xor_sync(0xffffffffu, m, off, 16));
    float ex = expf(o - m);
    float sum = ex;
#pragma unroll
    for (int off = 8; off > 0; off >>= 1)
        sum += __shfl_xor_sync(0xffffffffu, sum, off, 16);
    if (i < N_NODES) out[i * 16 + c] = o - m - logf(sum);
}

// ---------------- launch ----------------
extern "C" void kernel_launch(void* const* d_in, const int* in_sizes, int n_in,
                              void* d_out, int out_size) {
    const float* x   = (const float*)d_in[0];
    const void*  ei  = d_in[1];
    const float* W1  = (const float*)d_in[2];
    const float* a1s = (const float*)d_in[3];
    const float* a1d = (const float*)d_in[4];
    const float* b1  = (const float*)d_in[5];
    const float* W2  = (const float*)d_in[6];
    const float* a2s = (const float*)d_in[7];
    const float* a2d = (const float*)d_in[8];
    const float* b2  = (const float*)d_in[9];
    float* out = (float*)d_out;

    detect_kernel<<<1, 256>>>((const int*)ei);
    // CSR build (reused by both layers)
    zero_kernel<<<(N_NODES + 255) / 256, 256>>>();
    hist_kernel<<<(E_EDGES + 255) / 256, 256>>>(ei);
    scan1_kernel<<<SCAN_NB, 1024>>>();
    scan2_kernel<<<1, 32>>>();
    scan3_kernel<<<(N_NODES + 255) / 256, 256>>>();
    scatter_kernel<<<(E_EDGES + 255) / 256, 256>>>(ei);
    // layer 1
    gemm1_kernel<<<(N_NODES + 127) / 128, 256>>>(x, W1);
    node1_kernel<<<(N_NODES * 8 + 255) / 256, 256>>>(a1s, a1d);
    edge1_csr_kernel<<<(N_NODES * 32 + 255) / 256, 256>>>();
    final1_kernel<<<(N_NODES + 15) / 16, 256>>>(W2, b1, a2s, a2d);
    // layer 2
    edge2_csr_kernel<<<(N_NODES * 32 + 255) / 256, 256>>>();
    final2_kernel<<<(N_NODES + 15) / 16, 256>>>(b2, out);
}